// round 16
// baseline (speedup 1.0000x reference)
#include <cuda_runtime.h>
#include <cuda_fp16.h>
#include <cstdint>

// ---------------------------------------------------------------------------
// JanossyPoolingImproper — Round 16: R15 + persistent multi-tile GEMM3
// (4 m-tiles per CTA, continuous 32-stage pipeline, PROJ drain per tile).
//   P[node][j] = h[node] @ W1_block_j
//   GEMM2 (GATHER): A row (3n+p) = relu(sum_j P[idx[n,perm_p[j]]][j] + b1)
//   GEMM3 (persistent PROJ): relu(acc+b3) @ Wo -> atomicAdd(out[row/3])
// ---------------------------------------------------------------------------

#define H_DIM 512
#define F_DIM 128
#define MAX_N 100000
#define MAX_M (3 * MAX_N)
#define MAX_NH 50000
#define MAX_NH_PAD 50048

// ---- P-GEMM (KC=32) smem layout ----
#define KC 32
#define ROWB 80
#define A_TILE (128 * ROWB)          // 10240
#define B_TILE (256 * ROWB)          // 20480
#define SMEM_TOTAL (3 * A_TILE + 3 * B_TILE + 1024)   // 93184

// ---- big-GEMM (KC=64) smem layout ----
#define ROWB64 144                   // 128B data + 16 pad
#define A_T64 (128 * ROWB64)         // 18432
#define B_T64 (256 * ROWB64)         // 36864
#define SM64_B1 (3 * A_T64 + 3 * B_T64)   // 165888
#define SM64_PO (SM64_B1 + 2048)          // 167936
#define SM64_TOTAL (SM64_PO + 1024)       // 168960

__constant__ int c_perms[3][4] = {{0,1,2,3},{2,1,3,0},{3,1,0,2}};

__device__ __half g_Y0[(size_t)MAX_M * H_DIM];
__device__ __half g_h16[(size_t)MAX_NH * F_DIM];
__device__ __half g_P[(size_t)MAX_NH_PAD * 2048];   // [node][j][512]
__device__ __half g_Wt16[2][H_DIM * H_DIM];         // W2^T, W3^T
__device__ __half g_W1P[2048 * F_DIM];              // [j*512+n][k]
__device__ int    g_idx64_flag;

// ---------------------------- helpers -------------------------------------
__device__ __forceinline__ uint32_t smem_u32(const void* p) {
    uint32_t a;
    asm("{ .reg .u64 t; cvta.to.shared.u64 t, %1; cvt.u32.u64 %0, t; }" : "=r"(a) : "l"(p));
    return a;
}
__device__ __forceinline__ void cp16(uint32_t dst, const void* src, bool pred) {
    int bytes = pred ? 16 : 0;
    asm volatile("cp.async.ca.shared.global [%0], [%1], 16, %2;"
                 :: "r"(dst), "l"(src), "r"(bytes) : "memory");
}
__device__ __forceinline__ void cp_commit() {
    asm volatile("cp.async.commit_group;" ::: "memory");
}
template <int N>
__device__ __forceinline__ void cp_wait() {
    asm volatile("cp.async.wait_group %0;" :: "n"(N) : "memory");
}
__device__ __forceinline__ void ldm_x4(uint32_t* r, uint32_t addr) {
    asm volatile("ldmatrix.sync.aligned.m8n8.x4.shared.b16 {%0,%1,%2,%3}, [%4];"
                 : "=r"(r[0]), "=r"(r[1]), "=r"(r[2]), "=r"(r[3]) : "r"(addr));
}
__device__ __forceinline__ void mma_fp16(float* c, const uint32_t* a, const uint32_t* b) {
    asm volatile(
        "mma.sync.aligned.m16n8k16.row.col.f32.f16.f16.f32 "
        "{%0,%1,%2,%3}, {%4,%5,%6,%7}, {%8,%9}, {%0,%1,%2,%3};"
        : "+f"(c[0]), "+f"(c[1]), "+f"(c[2]), "+f"(c[3])
        : "r"(a[0]), "r"(a[1]), "r"(a[2]), "r"(a[3]), "r"(b[0]), "r"(b[1]));
}

// ---------------------------------------------------------------------------
__global__ void transpose_all_kernel(const float* __restrict__ W1,
                                     const float* __restrict__ W2,
                                     const float* __restrict__ W3,
                                     __half* __restrict__ W1P,
                                     __half* __restrict__ Wt2,
                                     __half* __restrict__ Wt3) {
    __shared__ float t[32][33];
    int z = blockIdx.z;
    const float* W = (z == 0) ? W1 : (z == 1) ? W2 : W3;
    int x = blockIdx.x * 32 + threadIdx.x;
    int y0 = blockIdx.y * 32;
#pragma unroll
    for (int i = threadIdx.y; i < 32; i += 8)
        t[i][threadIdx.x] = W[(y0 + i) * H_DIM + x];
    __syncthreads();
    if (z == 0) {
        int kprime = blockIdx.y * 32 + threadIdx.x;
        int j = kprime >> 7, kk = kprime & 127;
        int n0 = blockIdx.x * 32;
#pragma unroll
        for (int i = threadIdx.y; i < 32; i += 8)
            W1P[(size_t)(j * 512 + n0 + i) * F_DIM + kk] = __float2half_rn(t[threadIdx.x][i]);
    } else {
        __half* Wt = (z == 1) ? Wt2 : Wt3;
        int nx = blockIdx.y * 32 + threadIdx.x;
        int ny0 = blockIdx.x * 32;
#pragma unroll
        for (int i = threadIdx.y; i < 32; i += 8)
            Wt[(ny0 + i) * H_DIM + nx] = __float2half_rn(t[threadIdx.x][i]);
    }
}

__global__ void convert_h_detect_init_kernel(
    const float* __restrict__ h, int total4,
    const long long* __restrict__ idx64, int n_h,
    const float* __restrict__ bo, float* __restrict__ out, int N)
{
    if (blockIdx.x == 0) {
        long long v = idx64[threadIdx.x];
        int ok = (v >= 0 && v < (long long)n_h) ? 1 : 0;
        int all = __syncthreads_and(ok);
        if (threadIdx.x == 0) g_idx64_flag = all;
    }
    int tid = blockIdx.x * blockDim.x + threadIdx.x;
    if (tid < N) {
        out[(size_t)tid * 2 + 0] = __ldg(&bo[0]);
        out[(size_t)tid * 2 + 1] = __ldg(&bo[1]);
    }
    if (tid >= total4) return;
    float4 v = ((const float4*)h)[tid];
    ((__half2*)g_h16)[tid * 2 + 0] = __floats2half2_rn(v.x, v.y);
    ((__half2*)g_h16)[tid * 2 + 1] = __floats2half2_rn(v.z, v.w);
}

// ---------------------------------------------------------------------------
// Persistent P-GEMM (KC=32): 4 m-tiles per CTA, continuous pipeline.
// ---------------------------------------------------------------------------
__global__ __launch_bounds__(512, 1) void pgemm_kernel(
    const __half* __restrict__ Ah, const __half* __restrict__ Wt,
    __half* __restrict__ C, int Mh, int Mpad)
{
    extern __shared__ char smem[];
    uint32_t sA = smem_u32(smem);
    uint32_t sB = sA + 3 * A_TILE;
    const int NST = 16;

    int tid = threadIdx.x;
    int lane = tid & 31, wid = tid >> 5;
    int wm = wid >> 3, wn = wid & 7;
    int g = lane >> 2, t = lane & 3;
    int bn = blockIdx.x * 256;
    int mt0 = blockIdx.y * 4;

    int a_row = tid >> 2;
    int chunk = tid & 3;

    auto load_stage = [&](int st) {
        int buf = st % 3;
        int k0 = (st & 3) * KC;
        int rowg = (mt0 + (st >> 2)) * 128 + a_row;
        cp16(sA + buf * A_TILE + (uint32_t)(a_row * ROWB + chunk * 16),
             Ah + (size_t)rowg * F_DIM + k0 + chunk * 8, rowg < Mh);
#pragma unroll
        for (int i = 0; i < 2; i++) {
            int row = (tid >> 2) + i * 128;
            cp16(sB + buf * B_TILE + (uint32_t)(row * ROWB + chunk * 16),
                 Wt + (size_t)(bn + row) * F_DIM + k0 + chunk * 8, true);
        }
        cp_commit();
    };

    load_stage(0);
    load_stage(1);

    float acc[4][4][4];
#pragma unroll
    for (int i = 0; i < 4; i++)
#pragma unroll
        for (int j = 0; j < 4; j++)
#pragma unroll
            for (int r = 0; r < 4; r++) acc[i][j][r] = 0.0f;

    int a_row_off = (lane & 7) + ((lane >> 3) & 1) * 8;
    int a_col_off = (lane >> 4) * 8;
    int b_row_off = (lane & 7) + (lane >> 4) * 8;
    int b_col_off = ((lane >> 3) & 1) * 8;

    uint32_t a_frag[4], b_frag[2];
#pragma unroll
    for (int mf = 0; mf < 4; mf++)
        a_frag[mf] = (uint32_t)((wm * 64 + mf * 16 + a_row_off) * ROWB + a_col_off * 2);
#pragma unroll
    for (int nfp = 0; nfp < 2; nfp++)
        b_frag[nfp] = (uint32_t)((wn * 32 + nfp * 16 + b_row_off) * ROWB + b_col_off * 2);

    for (int st = 0; st < NST; st++) {
        cp_wait<1>();
        __syncthreads();
        if (st + 2 < NST) load_stage(st + 2);
        else              cp_commit();

        uint32_t aT = sA + (st % 3) * A_TILE;
        uint32_t bT = sB + (st % 3) * B_TILE;
#pragma unroll
        for (int ks = 0; ks < 2; ks++) {
            uint32_t koff = (uint32_t)(ks * 32);
            uint32_t af[4][4], bf[4][2];
#pragma unroll
            for (int mf = 0; mf < 4; mf++)
                ldm_x4(af[mf], aT + a_frag[mf] + koff);
#pragma unroll
            for (int nfp = 0; nfp < 2; nfp++) {
                uint32_t r4[4];
                ldm_x4(r4, bT + b_frag[nfp] + koff);
                bf[nfp * 2 + 0][0] = r4[0]; bf[nfp * 2 + 0][1] = r4[1];
                bf[nfp * 2 + 1][0] = r4[2]; bf[nfp * 2 + 1][1] = r4[3];
            }
#pragma unroll
            for (int mf = 0; mf < 4; mf++)
#pragma unroll
                for (int nf = 0; nf < 4; nf++)
                    mma_fp16(acc[mf][nf], af[mf], bf[nf]);
        }

        if ((st & 3) == 3) {
            int bm = (mt0 + (st >> 2)) * 128;
#pragma unroll
            for (int nf = 0; nf < 4; nf++) {
                int col = bn + wn * 32 + nf * 8 + 2 * t;
#pragma unroll
                for (int mf = 0; mf < 4; mf++) {
                    int row0 = bm + wm * 64 + mf * 16 + g;
                    if (row0 < Mpad)
                        *(__half2*)(C + (size_t)row0 * 2048 + col) =
                            __floats2half2_rn(acc[mf][nf][0], acc[mf][nf][1]);
                    if (row0 + 8 < Mpad)
                        *(__half2*)(C + (size_t)(row0 + 8) * 2048 + col) =
                            __floats2half2_rn(acc[mf][nf][2], acc[mf][nf][3]);
                    acc[mf][nf][0] = 0.f; acc[mf][nf][1] = 0.f;
                    acc[mf][nf][2] = 0.f; acc[mf][nf][3] = 0.f;
                }
            }
        }
    }
}

// ---------------------------------------------------------------------------
// GEMM2 (GATHER), KC=64 (8 stages). CTA 128x256, 512 thr, warp tile 64x32.
// Row r encodes (sample n = r/3, perm p = r%3). Unchanged from R15.
// ---------------------------------------------------------------------------
__global__ __launch_bounds__(512, 1) void gemm2_kernel(
    const __half* __restrict__ Wt, const float* __restrict__ bias,
    __half* __restrict__ C, int M,
    const void* __restrict__ idx, const float* __restrict__ b1)
{
    extern __shared__ char smem[];
    uint32_t sA = smem_u32(smem);
    uint32_t sB = sA + 3 * A_T64;
    float* b1s = (float*)(smem + SM64_B1);
    const int NS = 8;

    int tid = threadIdx.x;
    int lane = tid & 31, wid = tid >> 5;
    int wm = wid >> 3, wn = wid & 7;
    int g = lane >> 2, t = lane & 3;
    int bn = blockIdx.x * 256;
    int bm = blockIdx.y * 128;

    int a_row = tid >> 2;
    int chunk32 = tid & 3;
    bool a_val = (bm + a_row) < M;

    int chunk8 = tid & 7;
    int row8 = tid >> 3;

    uint32_t soff[4];
    uint4 areg[4];

    auto store_A = [&](int u) {
        int col0 = u * 32 + chunk32 * 8;
        uint4 o;
        __half2* oh = (__half2*)&o;
#pragma unroll
        for (int i = 0; i < 4; i++) {
            float2 f0 = __half22float2(((const __half2*)&areg[0])[i]);
            float2 f1 = __half22float2(((const __half2*)&areg[1])[i]);
            float2 f2 = __half22float2(((const __half2*)&areg[2])[i]);
            float2 f3 = __half22float2(((const __half2*)&areg[3])[i]);
            float vx = f0.x + f1.x + f2.x + f3.x + b1s[col0 + 2 * i];
            float vy = f0.y + f1.y + f2.y + f3.y + b1s[col0 + 2 * i + 1];
            oh[i] = __floats2half2_rn(fmaxf(vx, 0.f), fmaxf(vy, 0.f));
        }
        *(uint4*)(smem + ((u >> 1) & 1) * A_T64 + a_row * ROWB64
                  + (u & 1) * 64 + chunk32 * 16) = o;
    };
    auto ldg_sub = [&](int u) {
#pragma unroll
        for (int j = 0; j < 4; j++)
            areg[j] = __ldg((const uint4*)(g_P + soff[j] + u * 32));
    };
    auto load_B = [&](int s) {
        int buf = s % 3;
        int k0 = s * 64;
#pragma unroll
        for (int i = 0; i < 4; i++) {
            int row = row8 + i * 64;
            cp16(sB + buf * B_T64 + (uint32_t)(row * ROWB64 + chunk8 * 16),
                 Wt + (size_t)(bn + row) * H_DIM + k0 + chunk8 * 8, true);
        }
    };

    // -------- prologue --------
    b1s[tid & 511] = b1[tid & 511];
    {
        int row = a_val ? (bm + a_row) : 0;
        int n = (int)(((unsigned long long)row * 0x55555556ull) >> 32);
        int p = row - 3 * n;
        long long node[4];
        if (g_idx64_flag) {
#pragma unroll
            for (int s = 0; s < 4; s++) node[s] = ((const long long*)idx)[(long long)n * 4 + s];
        } else {
#pragma unroll
            for (int s = 0; s < 4; s++) node[s] = (long long)((const int*)idx)[n * 4 + s];
        }
#pragma unroll
        for (int j = 0; j < 4; j++)
            soff[j] = (uint32_t)(node[c_perms[p][j]] * 2048 + j * 512 + chunk32 * 8);
    }
    ldg_sub(0);
    __syncthreads();
    store_A(0);
    ldg_sub(1);
    store_A(1);
    ldg_sub(2);
    load_B(0); cp_commit();
    load_B(1); cp_commit();

    float acc[4][4][4];
#pragma unroll
    for (int i = 0; i < 4; i++)
#pragma unroll
        for (int j = 0; j < 4; j++)
#pragma unroll
            for (int r = 0; r < 4; r++) acc[i][j][r] = 0.0f;

    int a_row_off = (lane & 7) + ((lane >> 3) & 1) * 8;
    int a_col_off = (lane >> 4) * 8;
    int b_row_off = (lane & 7) + (lane >> 4) * 8;
    int b_col_off = ((lane >> 3) & 1) * 8;

    uint32_t a_frag[4], b_frag[2];
#pragma unroll
    for (int mf = 0; mf < 4; mf++)
        a_frag[mf] = (uint32_t)((wm * 64 + mf * 16 + a_row_off) * ROWB64 + a_col_off * 2);
#pragma unroll
    for (int nfp = 0; nfp < 2; nfp++)
        b_frag[nfp] = (uint32_t)((wn * 32 + nfp * 16 + b_row_off) * ROWB64 + b_col_off * 2);

    for (int s = 0; s < NS; s++) {
        cp_wait<1>();
        __syncthreads();
        if (s + 2 < NS) { load_B(s + 2); cp_commit(); }
        else            cp_commit();
        if (2 * s + 2 < 16) store_A(2 * s + 2);
        if (2 * s + 3 < 16) ldg_sub(2 * s + 3);

        uint32_t aT = sA + (s & 1) * A_T64;
        uint32_t bT = sB + (s % 3) * B_T64;
#pragma unroll
        for (int ks = 0; ks < 2; ks++) {
            uint32_t koff = (uint32_t)(ks * 32);
            uint32_t af[4][4], bf[4][2];
#pragma unroll
            for (int mf = 0; mf < 4; mf++)
                ldm_x4(af[mf], aT + a_frag[mf] + koff);
#pragma unroll
            for (int nfp = 0; nfp < 2; nfp++) {
                uint32_t r4[4];
                ldm_x4(r4, bT + b_frag[nfp] + koff);
                bf[nfp * 2 + 0][0] = r4[0]; bf[nfp * 2 + 0][1] = r4[1];
                bf[nfp * 2 + 1][0] = r4[2]; bf[nfp * 2 + 1][1] = r4[3];
            }
#pragma unroll
            for (int mf = 0; mf < 4; mf++)
#pragma unroll
                for (int nf = 0; nf < 4; nf++)
                    mma_fp16(acc[mf][nf], af[mf], bf[nf]);
        }
        if (2 * s + 3 < 16) store_A(2 * s + 3);
        if (2 * s + 4 < 16) ldg_sub(2 * s + 4);
#pragma unroll
        for (int ks = 2; ks < 4; ks++) {
            uint32_t koff = (uint32_t)(ks * 32);
            uint32_t af[4][4], bf[4][2];
#pragma unroll
            for (int mf = 0; mf < 4; mf++)
                ldm_x4(af[mf], aT + a_frag[mf] + koff);
#pragma unroll
            for (int nfp = 0; nfp < 2; nfp++) {
                uint32_t r4[4];
                ldm_x4(r4, bT + b_frag[nfp] + koff);
                bf[nfp * 2 + 0][0] = r4[0]; bf[nfp * 2 + 0][1] = r4[1];
                bf[nfp * 2 + 1][0] = r4[2]; bf[nfp * 2 + 1][1] = r4[3];
            }
#pragma unroll
            for (int mf = 0; mf < 4; mf++)
#pragma unroll
                for (int nf = 0; nf < 4; nf++)
                    mma_fp16(acc[mf][nf], af[mf], bf[nf]);
        }
    }

    // epilogue: bias + relu -> fp16 Y0
#pragma unroll
    for (int nf = 0; nf < 4; nf++) {
        int col = bn + wn * 32 + nf * 8 + 2 * t;
        float2 b2 = *(const float2*)(bias + col);
#pragma unroll
        for (int mf = 0; mf < 4; mf++) {
            int row0 = bm + wm * 64 + mf * 16 + g;
            float v0 = fmaxf(acc[mf][nf][0] + b2.x, 0.f);
            float v1 = fmaxf(acc[mf][nf][1] + b2.y, 0.f);
            float v2 = fmaxf(acc[mf][nf][2] + b2.x, 0.f);
            float v3 = fmaxf(acc[mf][nf][3] + b2.y, 0.f);
            if (row0 < M)
                *(__half2*)(C + (size_t)row0 * H_DIM + col) = __floats2half2_rn(v0, v1);
            if (row0 + 8 < M)
                *(__half2*)(C + (size_t)(row0 + 8) * H_DIM + col) = __floats2half2_rn(v2, v3);
        }
    }
}

// ---------------------------------------------------------------------------
// GEMM3 (persistent PROJ): 4 m-tiles per CTA in one continuous 32-stage
// pipeline (KC=64). Per-tile drain: relu(acc+b3) @ Wo -> atomicAdd(out[row/3]),
// overlapped with the next tile's in-flight cp.asyncs.
// ---------------------------------------------------------------------------
__global__ __launch_bounds__(512, 1) void gemm3_kernel(
    const __half* __restrict__ Ah, const __half* __restrict__ Wt,
    const float* __restrict__ bias, int M,
    const float* __restrict__ Wo, float* __restrict__ out)
{
    extern __shared__ char smem[];
    uint32_t sA = smem_u32(smem);
    uint32_t sB = sA + 3 * A_T64;
    float* po = (float*)(smem + SM64_PO);
    const int NST = 32;               // 4 m-tiles x 8 K-stages

    int tid = threadIdx.x;
    int lane = tid & 31, wid = tid >> 5;
    int wm = wid >> 3, wn = wid & 7;
    int g = lane >> 2, t = lane & 3;
    int bn = blockIdx.x * 256;
    int mt0 = blockIdx.y * 4;

    int chunk8 = tid & 7;
    int row8 = tid >> 3;

    auto load_stage = [&](int st) {
        int buf = st % 3;
        int k0 = (st & 7) * 64;
        int bmrow = (mt0 + (st >> 3)) * 128;
#pragma unroll
        for (int i = 0; i < 2; i++) {
            int row = row8 + i * 64;
            cp16(sA + buf * A_T64 + (uint32_t)(row * ROWB64 + chunk8 * 16),
                 Ah + (size_t)(bmrow + row) * H_DIM + k0 + chunk8 * 8,
                 (bmrow + row) < M);
        }
#pragma unroll
        for (int i = 0; i < 4; i++) {
            int row = row8 + i * 64;
            cp16(sB + buf * B_T64 + (uint32_t)(row * ROWB64 + chunk8 * 16),
                 Wt + (size_t)(bn + row) * H_DIM + k0 + chunk8 * 8, true);
        }
        cp_commit();
    };

    load_stage(0);
    load_stage(1);

    float acc[4][4][4];
#pragma unroll
    for (int i = 0; i < 4; i++)
#pragma unroll
        for (int j = 0; j < 4; j++)
#pragma unroll
            for (int r = 0; r < 4; r++) acc[i][j][r] = 0.0f;

    int a_row_off = (lane & 7) + ((lane >> 3) & 1) * 8;
    int a_col_off = (lane >> 4) * 8;
    int b_row_off = (lane & 7) + (lane >> 4) * 8;
    int b_col_off = ((lane >> 3) & 1) * 8;

    uint32_t a_frag[4], b_frag[2];
#pragma unroll
    for (int mf = 0; mf < 4; mf++)
        a_frag[mf] = (uint32_t)((wm * 64 + mf * 16 + a_row_off) * ROWB64 + a_col_off * 2);
#pragma unroll
    for (int nfp = 0; nfp < 2; nfp++)
        b_frag[nfp] = (uint32_t)((wn * 32 + nfp * 16 + b_row_off) * ROWB64 + b_col_off * 2);

    for (int st = 0; st < NST; st++) {
        cp_wait<1>();
        __syncthreads();
        if (st + 2 < NST) load_stage(st + 2);
        else              cp_commit();

        uint32_t aT = sA + (st % 3) * A_T64;
        uint32_t bT = sB + (st % 3) * B_T64;
#pragma unroll
        for (int ks = 0; ks < 4; ks++) {
            uint32_t koff = (uint32_t)(ks * 32);
            uint32_t af[4][4], bf[4][2];
#pragma unroll
            for (int mf = 0; mf < 4; mf++)
                ldm_x4(af[mf], aT + a_frag[mf] + koff);
#pragma unroll
            for (int nfp = 0; nfp < 2; nfp++) {
                uint32_t r4[4];
                ldm_x4(r4, bT + b_frag[nfp] + koff);
                bf[nfp * 2 + 0][0] = r4[0]; bf[nfp * 2 + 0][1] = r4[1];
                bf[nfp * 2 + 1][0] = r4[2]; bf[nfp * 2 + 1][1] = r4[3];
            }
#pragma unroll
            for (int mf = 0; mf < 4; mf++)
#pragma unroll
                for (int nf = 0; nf < 4; nf++)
                    mma_fp16(acc[mf][nf], af[mf], bf[nf]);
        }

        if ((st & 7) == 7) {
            // ---- drain this m-tile: relu(acc+b3) @ Wo -> out (atomics) ----
            int bm = (mt0 + (st >> 3)) * 128;
            __syncthreads();
            if (tid < 256) po[tid] = 0.f;
            __syncthreads();
#pragma unroll
            for (int mf = 0; mf < 4; mf++) {
#pragma unroll
                for (int sub = 0; sub < 2; sub++) {
                    float p0 = 0.f, p1 = 0.f;
#pragma unroll
                    for (int nf = 0; nf < 4; nf++) {
                        int col = bn + wn * 32 + nf * 8 + 2 * t;
                        float2 b2 = *(const float2*)(bias + col);
                        float v0 = fmaxf(acc[mf][nf][sub * 2 + 0] + b2.x, 0.f);
                        float v1 = fmaxf(acc[mf][nf][sub * 2 + 1] + b2.y, 0.f);
                        p0 += v0 * __ldg(&Wo[col * 2 + 0]) + v1 * __ldg(&Wo[(col + 1) * 2 + 0]);
                        p1 += v0 * __ldg(&Wo[col * 2 + 1]) + v1 * __ldg(&Wo[(col + 1) * 2 + 1]);
                    }
                    p0 += __shfl_xor_sync(0xFFFFFFFFu, p0, 1);
                    p0 += __shfl_xor_sync(0xFFFFFFFFu, p0, 2);
                    p1 += __shfl_xor_sync(0xFFFFFFFFu, p1, 1);
                    p1 += __shfl_xor_sync(0xFFFFFFFFu, p1, 2);
                    if (t == 0) {
                        int rloc = wm * 64 + mf * 16 + sub * 8 + g;
                        atomicAdd(&po[rloc * 2 + 0], p0);
                        atomicAdd(&po[rloc * 2 + 1], p1);
                    }
#pragma unroll
                    for (int nf = 0; nf < 4; nf++) {
                        acc[mf][nf][sub * 2 + 0] = 0.f;
                        acc[mf][nf][sub * 2 + 1] = 0.f;
                    }
                }
            }
            __syncthreads();
            if (tid < 256) {
                int rloc = tid >> 1, comp = tid & 1;
                int row = bm + rloc;
                if (row < M) {
                    int n = (int)(((unsigned long long)row * 0x55555556ull) >> 32);
                    atomicAdd(&out[(size_t)n * 2 + comp], po[rloc * 2 + comp]);
                }
            }
        }
    }
}

// ---------------------------------------------------------------------------
extern "C" void kernel_launch(void* const* d_in, const int* in_sizes, int n_in,
                              void* d_out, int out_size) {
    const float* h   = (const float*)d_in[0];
    const void*  idx = d_in[1];
    const float* W1  = (const float*)d_in[2];
    const float* b1  = (const float*)d_in[3];
    const float* W2  = (const float*)d_in[4];
    const float* b2  = (const float*)d_in[5];
    const float* W3  = (const float*)d_in[6];
    const float* b3  = (const float*)d_in[7];
    const float* Wo  = (const float*)d_in[8];
    const float* bo  = (const float*)d_in[9];
    float* out = (float*)d_out;

    int N   = in_sizes[1] / 4;
    int n_h = in_sizes[0] / F_DIM;
    int M   = 3 * N;

    __half *Y0, *h16, *P, *wt, *w1p;
    cudaGetSymbolAddress((void**)&Y0, g_Y0);
    cudaGetSymbolAddress((void**)&h16, g_h16);
    cudaGetSymbolAddress((void**)&P, g_P);
    cudaGetSymbolAddress((void**)&wt, g_Wt16);
    cudaGetSymbolAddress((void**)&w1p, g_W1P);
    __half* Wt2 = wt;
    __half* Wt3 = wt + H_DIM * H_DIM;

    cudaFuncSetAttribute(pgemm_kernel,
                         cudaFuncAttributeMaxDynamicSharedMemorySize, SMEM_TOTAL);
    cudaFuncSetAttribute(gemm2_kernel,
                         cudaFuncAttributeMaxDynamicSharedMemorySize, SM64_TOTAL);
    cudaFuncSetAttribute(gemm3_kernel,
                         cudaFuncAttributeMaxDynamicSharedMemorySize, SM64_TOTAL);

    // Launch order: capture slot (#4) = GEMM2.
    dim3 tb(32, 8), tg(16, 16, 3);
    transpose_all_kernel<<<tg, tb>>>(W1, W2, W3, w1p, Wt2, Wt3);            // 1
    int h4 = in_sizes[0] / 4;
    int cblocks = (h4 > N ? h4 : N);
    convert_h_detect_init_kernel<<<(cblocks + 255) / 256, 256>>>(
        h, h4, (const long long*)idx, n_h, bo, out, N);                     // 2

    // 3: persistent P-GEMM
    int mtiles_p = (n_h + 127) / 128;
    int mpad = mtiles_p * 128;
    dim3 pgrid(2048 / 256, (mtiles_p + 3) / 4);
    pgemm_kernel<<<pgrid, 512, SMEM_TOTAL>>>(h16, w1p, P, n_h, mpad);

    // 4: layer 2 (gathered A from P) -> Y0
    int mtiles = (M + 127) / 128;                  // 2344
    dim3 g2grid(H_DIM / 256, mtiles);
    gemm2_kernel<<<g2grid, 512, SM64_TOTAL>>>(Wt2, b2, Y0, M, idx, b1);

    // 5: layer 3 persistent (4 m-tiles/CTA), projection into out
    dim3 g3grid(H_DIM / 256, (mtiles + 3) / 4);    // (2, 586)
    gemm3_kernel<<<g3grid, 512, SM64_TOTAL>>>(Y0, Wt3, b3, M, Wo, out);
}

// round 17
// speedup vs baseline: 1.0287x; 1.0287x over previous
#include <cuda_runtime.h>
#include <cuda_fp16.h>
#include <cstdint>

// ---------------------------------------------------------------------------
// JanossyPoolingImproper — Round 17: R15 restored (best structure) + PROJ
// epilogue loop-interchange: bias/Wo loaded once per nf (8x fewer epilogue
// LDGs), accumulation order and results bit-identical.
//   P[node][j] = h[node] @ W1_block_j
//   GEMM2 (GATHER): A row (3n+p) = relu(sum_j P[idx[n,perm_p[j]]][j] + b1)
//   GEMM3 (PROJ):   epilogue relu(acc+b3) @ Wo -> atomicAdd(out[row/3])
// ---------------------------------------------------------------------------

#define H_DIM 512
#define F_DIM 128
#define MAX_N 100000
#define MAX_M (3 * MAX_N)
#define MAX_NH 50000
#define MAX_NH_PAD 50048

// ---- P-GEMM (KC=32) smem layout ----
#define KC 32
#define ROWB 80
#define A_TILE (128 * ROWB)          // 10240
#define B_TILE (256 * ROWB)          // 20480
#define SMEM_TOTAL (3 * A_TILE + 3 * B_TILE + 1024)   // 93184

// ---- big-GEMM (KC=64) smem layout ----
#define ROWB64 144                   // 128B data + 16 pad
#define A_T64 (128 * ROWB64)         // 18432
#define B_T64 (256 * ROWB64)         // 36864
#define SM64_B1 (3 * A_T64 + 3 * B_T64)   // 165888
#define SM64_PO (SM64_B1 + 2048)          // 167936
#define SM64_TOTAL (SM64_PO + 1024)       // 168960

__constant__ int c_perms[3][4] = {{0,1,2,3},{2,1,3,0},{3,1,0,2}};

__device__ __half g_Y0[(size_t)MAX_M * H_DIM];
__device__ __half g_h16[(size_t)MAX_NH * F_DIM];
__device__ __half g_P[(size_t)MAX_NH_PAD * 2048];   // [node][j][512]
__device__ __half g_Wt16[2][H_DIM * H_DIM];         // W2^T, W3^T
__device__ __half g_W1P[2048 * F_DIM];              // [j*512+n][k]
__device__ int    g_idx64_flag;

// ---------------------------- helpers -------------------------------------
__device__ __forceinline__ uint32_t smem_u32(const void* p) {
    uint32_t a;
    asm("{ .reg .u64 t; cvta.to.shared.u64 t, %1; cvt.u32.u64 %0, t; }" : "=r"(a) : "l"(p));
    return a;
}
__device__ __forceinline__ void cp16(uint32_t dst, const void* src, bool pred) {
    int bytes = pred ? 16 : 0;
    asm volatile("cp.async.ca.shared.global [%0], [%1], 16, %2;"
                 :: "r"(dst), "l"(src), "r"(bytes) : "memory");
}
__device__ __forceinline__ void cp_commit() {
    asm volatile("cp.async.commit_group;" ::: "memory");
}
template <int N>
__device__ __forceinline__ void cp_wait() {
    asm volatile("cp.async.wait_group %0;" :: "n"(N) : "memory");
}
__device__ __forceinline__ void ldm_x4(uint32_t* r, uint32_t addr) {
    asm volatile("ldmatrix.sync.aligned.m8n8.x4.shared.b16 {%0,%1,%2,%3}, [%4];"
                 : "=r"(r[0]), "=r"(r[1]), "=r"(r[2]), "=r"(r[3]) : "r"(addr));
}
__device__ __forceinline__ void mma_fp16(float* c, const uint32_t* a, const uint32_t* b) {
    asm volatile(
        "mma.sync.aligned.m16n8k16.row.col.f32.f16.f16.f32 "
        "{%0,%1,%2,%3}, {%4,%5,%6,%7}, {%8,%9}, {%0,%1,%2,%3};"
        : "+f"(c[0]), "+f"(c[1]), "+f"(c[2]), "+f"(c[3])
        : "r"(a[0]), "r"(a[1]), "r"(a[2]), "r"(a[3]), "r"(b[0]), "r"(b[1]));
}

// ---------------------------------------------------------------------------
__global__ void transpose_all_kernel(const float* __restrict__ W1,
                                     const float* __restrict__ W2,
                                     const float* __restrict__ W3,
                                     __half* __restrict__ W1P,
                                     __half* __restrict__ Wt2,
                                     __half* __restrict__ Wt3) {
    __shared__ float t[32][33];
    int z = blockIdx.z;
    const float* W = (z == 0) ? W1 : (z == 1) ? W2 : W3;
    int x = blockIdx.x * 32 + threadIdx.x;
    int y0 = blockIdx.y * 32;
#pragma unroll
    for (int i = threadIdx.y; i < 32; i += 8)
        t[i][threadIdx.x] = W[(y0 + i) * H_DIM + x];
    __syncthreads();
    if (z == 0) {
        int kprime = blockIdx.y * 32 + threadIdx.x;
        int j = kprime >> 7, kk = kprime & 127;
        int n0 = blockIdx.x * 32;
#pragma unroll
        for (int i = threadIdx.y; i < 32; i += 8)
            W1P[(size_t)(j * 512 + n0 + i) * F_DIM + kk] = __float2half_rn(t[threadIdx.x][i]);
    } else {
        __half* Wt = (z == 1) ? Wt2 : Wt3;
        int nx = blockIdx.y * 32 + threadIdx.x;
        int ny0 = blockIdx.x * 32;
#pragma unroll
        for (int i = threadIdx.y; i < 32; i += 8)
            Wt[(ny0 + i) * H_DIM + nx] = __float2half_rn(t[threadIdx.x][i]);
    }
}

__global__ void convert_h_detect_init_kernel(
    const float* __restrict__ h, int total4,
    const long long* __restrict__ idx64, int n_h,
    const float* __restrict__ bo, float* __restrict__ out, int N)
{
    if (blockIdx.x == 0) {
        long long v = idx64[threadIdx.x];
        int ok = (v >= 0 && v < (long long)n_h) ? 1 : 0;
        int all = __syncthreads_and(ok);
        if (threadIdx.x == 0) g_idx64_flag = all;
    }
    int tid = blockIdx.x * blockDim.x + threadIdx.x;
    if (tid < N) {
        out[(size_t)tid * 2 + 0] = __ldg(&bo[0]);
        out[(size_t)tid * 2 + 1] = __ldg(&bo[1]);
    }
    if (tid >= total4) return;
    float4 v = ((const float4*)h)[tid];
    ((__half2*)g_h16)[tid * 2 + 0] = __floats2half2_rn(v.x, v.y);
    ((__half2*)g_h16)[tid * 2 + 1] = __floats2half2_rn(v.z, v.w);
}

// ---------------------------------------------------------------------------
// Persistent P-GEMM (KC=32): 4 m-tiles per CTA, continuous pipeline.
// ---------------------------------------------------------------------------
__global__ __launch_bounds__(512, 1) void pgemm_kernel(
    const __half* __restrict__ Ah, const __half* __restrict__ Wt,
    __half* __restrict__ C, int Mh, int Mpad)
{
    extern __shared__ char smem[];
    uint32_t sA = smem_u32(smem);
    uint32_t sB = sA + 3 * A_TILE;
    const int NST = 16;

    int tid = threadIdx.x;
    int lane = tid & 31, wid = tid >> 5;
    int wm = wid >> 3, wn = wid & 7;
    int g = lane >> 2, t = lane & 3;
    int bn = blockIdx.x * 256;
    int mt0 = blockIdx.y * 4;

    int a_row = tid >> 2;
    int chunk = tid & 3;

    auto load_stage = [&](int st) {
        int buf = st % 3;
        int k0 = (st & 3) * KC;
        int rowg = (mt0 + (st >> 2)) * 128 + a_row;
        cp16(sA + buf * A_TILE + (uint32_t)(a_row * ROWB + chunk * 16),
             Ah + (size_t)rowg * F_DIM + k0 + chunk * 8, rowg < Mh);
#pragma unroll
        for (int i = 0; i < 2; i++) {
            int row = (tid >> 2) + i * 128;
            cp16(sB + buf * B_TILE + (uint32_t)(row * ROWB + chunk * 16),
                 Wt + (size_t)(bn + row) * F_DIM + k0 + chunk * 8, true);
        }
        cp_commit();
    };

    load_stage(0);
    load_stage(1);

    float acc[4][4][4];
#pragma unroll
    for (int i = 0; i < 4; i++)
#pragma unroll
        for (int j = 0; j < 4; j++)
#pragma unroll
            for (int r = 0; r < 4; r++) acc[i][j][r] = 0.0f;

    int a_row_off = (lane & 7) + ((lane >> 3) & 1) * 8;
    int a_col_off = (lane >> 4) * 8;
    int b_row_off = (lane & 7) + (lane >> 4) * 8;
    int b_col_off = ((lane >> 3) & 1) * 8;

    uint32_t a_frag[4], b_frag[2];
#pragma unroll
    for (int mf = 0; mf < 4; mf++)
        a_frag[mf] = (uint32_t)((wm * 64 + mf * 16 + a_row_off) * ROWB + a_col_off * 2);
#pragma unroll
    for (int nfp = 0; nfp < 2; nfp++)
        b_frag[nfp] = (uint32_t)((wn * 32 + nfp * 16 + b_row_off) * ROWB + b_col_off * 2);

    for (int st = 0; st < NST; st++) {
        cp_wait<1>();
        __syncthreads();
        if (st + 2 < NST) load_stage(st + 2);
        else              cp_commit();

        uint32_t aT = sA + (st % 3) * A_TILE;
        uint32_t bT = sB + (st % 3) * B_TILE;
#pragma unroll
        for (int ks = 0; ks < 2; ks++) {
            uint32_t koff = (uint32_t)(ks * 32);
            uint32_t af[4][4], bf[4][2];
#pragma unroll
            for (int mf = 0; mf < 4; mf++)
                ldm_x4(af[mf], aT + a_frag[mf] + koff);
#pragma unroll
            for (int nfp = 0; nfp < 2; nfp++) {
                uint32_t r4[4];
                ldm_x4(r4, bT + b_frag[nfp] + koff);
                bf[nfp * 2 + 0][0] = r4[0]; bf[nfp * 2 + 0][1] = r4[1];
                bf[nfp * 2 + 1][0] = r4[2]; bf[nfp * 2 + 1][1] = r4[3];
            }
#pragma unroll
            for (int mf = 0; mf < 4; mf++)
#pragma unroll
                for (int nf = 0; nf < 4; nf++)
                    mma_fp16(acc[mf][nf], af[mf], bf[nf]);
        }

        if ((st & 3) == 3) {
            int bm = (mt0 + (st >> 2)) * 128;
#pragma unroll
            for (int nf = 0; nf < 4; nf++) {
                int col = bn + wn * 32 + nf * 8 + 2 * t;
#pragma unroll
                for (int mf = 0; mf < 4; mf++) {
                    int row0 = bm + wm * 64 + mf * 16 + g;
                    if (row0 < Mpad)
                        *(__half2*)(C + (size_t)row0 * 2048 + col) =
                            __floats2half2_rn(acc[mf][nf][0], acc[mf][nf][1]);
                    if (row0 + 8 < Mpad)
                        *(__half2*)(C + (size_t)(row0 + 8) * 2048 + col) =
                            __floats2half2_rn(acc[mf][nf][2], acc[mf][nf][3]);
                    acc[mf][nf][0] = 0.f; acc[mf][nf][1] = 0.f;
                    acc[mf][nf][2] = 0.f; acc[mf][nf][3] = 0.f;
                }
            }
        }
    }
}

// ---------------------------------------------------------------------------
// Unified big GEMM, KC=64 (8 stages). CTA 128x256, 512 thr, warp tile 64x32.
// Row r encodes (sample n = r/3, perm p = r%3).
// GATHER: converted-A produced in 32-col substages, interleaved between the
//         two MMA half-blocks of each stage; LDGs one substage ahead.
// PROJ:   epilogue relu(acc+bias) @ Wo -> atomicAdd(out), bias/Wo hoisted.
// ---------------------------------------------------------------------------
template <int GATHER, int PROJ>
__global__ __launch_bounds__(512, 1) void gemm_fused_kernel(
    const __half* __restrict__ Ah, const __half* __restrict__ Wt,
    const float* __restrict__ bias, __half* __restrict__ C,
    int M, const void* __restrict__ idx, const float* __restrict__ b1,
    const float* __restrict__ Wo, float* __restrict__ out)
{
    extern __shared__ char smem[];
    uint32_t sA = smem_u32(smem);
    uint32_t sB = sA + 3 * A_T64;
    float* b1s = (float*)(smem + SM64_B1);
    float* po  = (float*)(smem + SM64_PO);
    const int NS = 8;                 // 512 / 64

    int tid = threadIdx.x;
    int lane = tid & 31, wid = tid >> 5;
    int wm = wid >> 3, wn = wid & 7;
    int g = lane >> 2, t = lane & 3;
    int bn = blockIdx.x * 256;
    int bm = blockIdx.y * 128;

    int a_row = tid >> 2;
    int chunk32 = tid & 3;
    bool a_val = (bm + a_row) < M;

    int chunk8 = tid & 7;
    int row8 = tid >> 3;              // 0..63

    uint32_t soff[4];
    uint4 areg[4];

    auto store_A = [&](int u) {
        int col0 = u * 32 + chunk32 * 8;
        uint4 o;
        __half2* oh = (__half2*)&o;
#pragma unroll
        for (int i = 0; i < 4; i++) {
            float2 f0 = __half22float2(((const __half2*)&areg[0])[i]);
            float2 f1 = __half22float2(((const __half2*)&areg[1])[i]);
            float2 f2 = __half22float2(((const __half2*)&areg[2])[i]);
            float2 f3 = __half22float2(((const __half2*)&areg[3])[i]);
            float vx = f0.x + f1.x + f2.x + f3.x + b1s[col0 + 2 * i];
            float vy = f0.y + f1.y + f2.y + f3.y + b1s[col0 + 2 * i + 1];
            oh[i] = __floats2half2_rn(fmaxf(vx, 0.f), fmaxf(vy, 0.f));
        }
        *(uint4*)(smem + ((u >> 1) & 1) * A_T64 + a_row * ROWB64
                  + (u & 1) * 64 + chunk32 * 16) = o;
    };
    auto ldg_sub = [&](int u) {
#pragma unroll
        for (int j = 0; j < 4; j++)
            areg[j] = __ldg((const uint4*)(g_P + soff[j] + u * 32));
    };

    auto load_B = [&](int s) {
        int buf = s % 3;
        int k0 = s * 64;
#pragma unroll
        for (int i = 0; i < 4; i++) {
            int row = row8 + i * 64;
            cp16(sB + buf * B_T64 + (uint32_t)(row * ROWB64 + chunk8 * 16),
                 Wt + (size_t)(bn + row) * H_DIM + k0 + chunk8 * 8, true);
        }
    };
    auto load_A_cp = [&](int s) {
        int buf = s % 3;
        int k0 = s * 64;
#pragma unroll
        for (int i = 0; i < 2; i++) {
            int row = row8 + i * 64;
            cp16(sA + buf * A_T64 + (uint32_t)(row * ROWB64 + chunk8 * 16),
                 Ah + (size_t)(bm + row) * H_DIM + k0 + chunk8 * 8, (bm + row) < M);
        }
    };

    // -------- prologue --------
    if (GATHER) {
        b1s[tid & 511] = b1[tid & 511];
        int row = a_val ? (bm + a_row) : 0;
        int n = (int)(((unsigned long long)row * 0x55555556ull) >> 32);
        int p = row - 3 * n;
        long long node[4];
        if (g_idx64_flag) {
#pragma unroll
            for (int s = 0; s < 4; s++) node[s] = ((const long long*)idx)[(long long)n * 4 + s];
        } else {
#pragma unroll
            for (int s = 0; s < 4; s++) node[s] = (long long)((const int*)idx)[n * 4 + s];
        }
#pragma unroll
        for (int j = 0; j < 4; j++)
            soff[j] = (uint32_t)(node[c_perms[p][j]] * 2048 + j * 512 + chunk32 * 8);
        ldg_sub(0);
        __syncthreads();              // b1s visible
        store_A(0);
        ldg_sub(1);
        store_A(1);                   // one exposed LDG latency in prologue only
        ldg_sub(2);
    } else {
        load_A_cp(0);
    }
    load_B(0); cp_commit();
    if (!GATHER) load_A_cp(1);
    load_B(1); cp_commit();

    float acc[4][4][4];
#pragma unroll
    for (int i = 0; i < 4; i++)
#pragma unroll
        for (int j = 0; j < 4; j++)
#pragma unroll
            for (int r = 0; r < 4; r++) acc[i][j][r] = 0.0f;

    int a_row_off = (lane & 7) + ((lane >> 3) & 1) * 8;
    int a_col_off = (lane >> 4) * 8;
    int b_row_off = (lane & 7) + (lane >> 4) * 8;
    int b_col_off = ((lane >> 3) & 1) * 8;

    uint32_t a_frag[4], b_frag[2];
#pragma unroll
    for (int mf = 0; mf < 4; mf++)
        a_frag[mf] = (uint32_t)((wm * 64 + mf * 16 + a_row_off) * ROWB64 + a_col_off * 2);
#pragma unroll
    for (int nfp = 0; nfp < 2; nfp++)
        b_frag[nfp] = (uint32_t)((wn * 32 + nfp * 16 + b_row_off) * ROWB64 + b_col_off * 2);

    for (int s = 0; s < NS; s++) {
        cp_wait<1>();
        __syncthreads();    // B[s] visible; A stage s (STS) visible
        if (!GATHER && s + 2 < NS) load_A_cp(s + 2);
        if (s + 2 < NS) { load_B(s + 2); cp_commit(); }
        else            cp_commit();
        if (GATHER) {
            if (2 * s + 2 < 16) store_A(2 * s + 2);
            if (2 * s + 3 < 16) ldg_sub(2 * s + 3);
        }

        uint32_t aT = sA + (GATHER ? (s & 1) : (s % 3)) * A_T64;
        uint32_t bT = sB + (s % 3) * B_T64;
        // ---- first half: ks = 0,1 ----
#pragma unroll
        for (int ks = 0; ks < 2; ks++) {
            uint32_t koff = (uint32_t)(ks * 32);
            uint32_t af[4][4], bf[4][2];
#pragma unroll
            for (int mf = 0; mf < 4; mf++)
                ldm_x4(af[mf], aT + a_frag[mf] + koff);
#pragma unroll
            for (int nfp = 0; nfp < 2; nfp++) {
                uint32_t r4[4];
                ldm_x4(r4, bT + b_frag[nfp] + koff);
                bf[nfp * 2 + 0][0] = r4[0]; bf[nfp * 2 + 0][1] = r4[1];
                bf[nfp * 2 + 1][0] = r4[2]; bf[nfp * 2 + 1][1] = r4[3];
            }
#pragma unroll
            for (int mf = 0; mf < 4; mf++)
#pragma unroll
                for (int nf = 0; nf < 4; nf++)
                    mma_fp16(acc[mf][nf], af[mf], bf[nf]);
        }
        if (GATHER) {
            if (2 * s + 3 < 16) store_A(2 * s + 3);
            if (2 * s + 4 < 16) ldg_sub(2 * s + 4);
        }
        // ---- second half: ks = 2,3 ----
#pragma unroll
        for (int ks = 2; ks < 4; ks++) {
            uint32_t koff = (uint32_t)(ks * 32);
            uint32_t af[4][4], bf[4][2];
#pragma unroll
            for (int mf = 0; mf < 4; mf++)
                ldm_x4(af[mf], aT + a_frag[mf] + koff);
#pragma unroll
            for (int nfp = 0; nfp < 2; nfp++) {
                uint32_t r4[4];
                ldm_x4(r4, bT + b_frag[nfp] + koff);
                bf[nfp * 2 + 0][0] = r4[0]; bf[nfp * 2 + 0][1] = r4[1];
                bf[nfp * 2 + 1][0] = r4[2]; bf[nfp * 2 + 1][1] = r4[3];
            }
#pragma unroll
            for (int mf = 0; mf < 4; mf++)
#pragma unroll
                for (int nf = 0; nf < 4; nf++)
                    mma_fp16(acc[mf][nf], af[mf], bf[nf]);
        }
    }

    if (PROJ) {
        __syncthreads();
        if (tid < 256) po[tid] = 0.f;
        __syncthreads();
        // loop-interchanged projection: load bias/Wo once per nf (8x fewer
        // LDGs); nf accumulation order preserved -> bit-identical results.
        float pacc[2][4][2];          // [comp][mf][sub]
#pragma unroll
        for (int mf = 0; mf < 4; mf++)
#pragma unroll
            for (int sub = 0; sub < 2; sub++) {
                pacc[0][mf][sub] = 0.f;
                pacc[1][mf][sub] = 0.f;
            }
#pragma unroll
        for (int nf = 0; nf < 4; nf++) {
            int col = bn + wn * 32 + nf * 8 + 2 * t;
            float2 b2 = *(const float2*)(bias + col);
            float w00 = __ldg(&Wo[col * 2 + 0]);
            float w01 = __ldg(&Wo[col * 2 + 1]);
            float w10 = __ldg(&Wo[(col + 1) * 2 + 0]);
            float w11 = __ldg(&Wo[(col + 1) * 2 + 1]);
#pragma unroll
            for (int mf = 0; mf < 4; mf++)
#pragma unroll
                for (int sub = 0; sub < 2; sub++) {
                    float v0 = fmaxf(acc[mf][nf][sub * 2 + 0] + b2.x, 0.f);
                    float v1 = fmaxf(acc[mf][nf][sub * 2 + 1] + b2.y, 0.f);
                    pacc[0][mf][sub] += v0 * w00 + v1 * w10;
                    pacc[1][mf][sub] += v0 * w01 + v1 * w11;
                }
        }
#pragma unroll
        for (int mf = 0; mf < 4; mf++)
#pragma unroll
            for (int sub = 0; sub < 2; sub++) {
                float p0 = pacc[0][mf][sub];
                float p1 = pacc[1][mf][sub];
                p0 += __shfl_xor_sync(0xFFFFFFFFu, p0, 1);
                p0 += __shfl_xor_sync(0xFFFFFFFFu, p0, 2);
                p1 += __shfl_xor_sync(0xFFFFFFFFu, p1, 1);
                p1 += __shfl_xor_sync(0xFFFFFFFFu, p1, 2);
                if (t == 0) {
                    int rloc = wm * 64 + mf * 16 + sub * 8 + g;
                    atomicAdd(&po[rloc * 2 + 0], p0);
                    atomicAdd(&po[rloc * 2 + 1], p1);
                }
            }
        __syncthreads();
        if (tid < 256) {
            int rloc = tid >> 1, comp = tid & 1;
            int row = bm + rloc;
            if (row < M) {
                int n = (int)(((unsigned long long)row * 0x55555556ull) >> 32);
                atomicAdd(&out[(size_t)n * 2 + comp], po[rloc * 2 + comp]);
            }
        }
    } else {
#pragma unroll
        for (int nf = 0; nf < 4; nf++) {
            int col = bn + wn * 32 + nf * 8 + 2 * t;
            float2 b2 = *(const float2*)(bias + col);
#pragma unroll
            for (int mf = 0; mf < 4; mf++) {
                int row0 = bm + wm * 64 + mf * 16 + g;
                float v0 = fmaxf(acc[mf][nf][0] + b2.x, 0.f);
                float v1 = fmaxf(acc[mf][nf][1] + b2.y, 0.f);
                float v2 = fmaxf(acc[mf][nf][2] + b2.x, 0.f);
                float v3 = fmaxf(acc[mf][nf][3] + b2.y, 0.f);
                if (row0 < M)
                    *(__half2*)(C + (size_t)row0 * H_DIM + col) = __floats2half2_rn(v0, v1);
                if (row0 + 8 < M)
                    *(__half2*)(C + (size_t)(row0 + 8) * H_DIM + col) = __floats2half2_rn(v2, v3);
            }
        }
    }
}

// ---------------------------------------------------------------------------
extern "C" void kernel_launch(void* const* d_in, const int* in_sizes, int n_in,
                              void* d_out, int out_size) {
    const float* h   = (const float*)d_in[0];
    const void*  idx = d_in[1];
    const float* W1  = (const float*)d_in[2];
    const float* b1  = (const float*)d_in[3];
    const float* W2  = (const float*)d_in[4];
    const float* b2  = (const float*)d_in[5];
    const float* W3  = (const float*)d_in[6];
    const float* b3  = (const float*)d_in[7];
    const float* Wo  = (const float*)d_in[8];
    const float* bo  = (const float*)d_in[9];
    float* out = (float*)d_out;

    int N   = in_sizes[1] / 4;
    int n_h = in_sizes[0] / F_DIM;
    int M   = 3 * N;

    __half *Y0, *h16, *P, *wt, *w1p;
    cudaGetSymbolAddress((void**)&Y0, g_Y0);
    cudaGetSymbolAddress((void**)&h16, g_h16);
    cudaGetSymbolAddress((void**)&P, g_P);
    cudaGetSymbolAddress((void**)&wt, g_Wt16);
    cudaGetSymbolAddress((void**)&w1p, g_W1P);
    __half* Wt2 = wt;
    __half* Wt3 = wt + H_DIM * H_DIM;

    cudaFuncSetAttribute(pgemm_kernel,
                         cudaFuncAttributeMaxDynamicSharedMemorySize, SMEM_TOTAL);
    cudaFuncSetAttribute(gemm_fused_kernel<1, 0>,
                         cudaFuncAttributeMaxDynamicSharedMemorySize, SM64_TOTAL);
    cudaFuncSetAttribute(gemm_fused_kernel<0, 1>,
                         cudaFuncAttributeMaxDynamicSharedMemorySize, SM64_TOTAL);

    // Launch order: capture slot (#4) = GEMM2.
    dim3 tb(32, 8), tg(16, 16, 3);
    transpose_all_kernel<<<tg, tb>>>(W1, W2, W3, w1p, Wt2, Wt3);            // 1
    int h4 = in_sizes[0] / 4;
    int cblocks = (h4 > N ? h4 : N);
    convert_h_detect_init_kernel<<<(cblocks + 255) / 256, 256>>>(
        h, h4, (const long long*)idx, n_h, bo, out, N);                     // 2

    // 3: persistent P-GEMM
    int mtiles_p = (n_h + 127) / 128;
    int mpad = mtiles_p * 128;
    dim3 pgrid(2048 / 256, (mtiles_p + 3) / 4);
    pgemm_kernel<<<pgrid, 512, SMEM_TOTAL>>>(h16, w1p, P, n_h, mpad);

    // 4: layer 2 (gathered A from P) -> Y0
    int mtiles = (M + 127) / 128;
    dim3 ggrid(H_DIM / 256, mtiles);
    gemm_fused_kernel<1, 0><<<ggrid, 512, SM64_TOTAL>>>(
        nullptr, Wt2, b2, Y0, M, idx, b1, nullptr, nullptr);

    // 5: layer 3 (dense A = Y0), projection epilogue into out
    gemm_fused_kernel<0, 1><<<ggrid, 512, SM64_TOTAL>>>(
        Y0, Wt3, b3, nullptr, M, nullptr, nullptr, Wo, out);
}